// round 6
// baseline (speedup 1.0000x reference)
#include <cuda_runtime.h>
#include <math.h>
#include <stdint.h>

#define NN 50000
#define NE 800000
#define HID 64
#define IN_DIM 128
#define ED 32
#define NEG 0.2f

// ---------------- device scratch ----------------
__device__ __align__(16) float g_h[NN * HID];     // current layer node transform
__device__ __align__(16) float g_x1[NN * HID];    // layer-1 output
__device__ __align__(16) float g_x2[NN * HID];    // layer-2 output
__device__ __align__(16) float g_p[NN * HID];     // x2 @ Wc1[0:64] + bc1
__device__ __align__(16) float g_q[NN * HID];     // x2 @ Wc1[64:128]
__device__ float g_ssrc[NN];
__device__ float g_sdst[NN];
__device__ int g_deg[NN];
__device__ int g_cnt[NN];
__device__ int g_off[NN + 1];
__device__ int g_src_csr[NE];
__device__ float g_hd1[NE];                       // ea . wvec1, CSR order
__device__ float g_hd2[NE];                       // ea . wvec2, CSR order
__device__ float g_wvec1[ED];
__device__ float g_wvec2[ED];

__device__ __forceinline__ float lrelu(float x) { return x > 0.f ? x : NEG * x; }

// ---- packed fp32x2 helpers (Blackwell FFMA2: 2x fp32 FMA per issue slot) ----
__device__ __forceinline__ void fma2(unsigned long long& d, unsigned long long a,
                                     unsigned long long b) {
    asm("fma.rn.f32x2 %0, %1, %2, %0;" : "+l"(d) : "l"(a), "l"(b));
}
__device__ __forceinline__ unsigned long long dup2(float v) {
    unsigned long long d;
    unsigned u = __float_as_uint(v);
    asm("mov.b64 %0, {%1, %1};" : "=l"(d) : "r"(u));
    return d;
}
__device__ __forceinline__ float2 unp(unsigned long long v) {
    unsigned lo, hi;
    asm("mov.b64 {%0, %1}, %2;" : "=r"(lo), "=r"(hi) : "l"(v));
    return make_float2(__uint_as_float(lo), __uint_as_float(hi));
}

// ---------------- CSR build ----------------
__global__ void k_zero() {
    int n = blockIdx.x * blockDim.x + threadIdx.x;
    if (n < NN) { g_deg[n] = 0; g_cnt[n] = 0; }
}

__global__ void k_count_deg(const int* __restrict__ ei) {
    int e = blockIdx.x * blockDim.x + threadIdx.x;
    if (e < NE) atomicAdd(&g_deg[ei[NE + e]], 1);
}

// fast single-block exclusive scan
__global__ __launch_bounds__(1024) void k_scan() {
    const int PER = (NN + 1023) / 1024;   // 49
    int tid = threadIdx.x;
    int lane = tid & 31, wid = tid >> 5;
    int start = tid * PER;
    int stop = min(start + PER, NN);

    int sum = 0;
    for (int i = start; i < stop; i++) sum += g_deg[i];

    int v = sum;
    #pragma unroll
    for (int o = 1; o < 32; o <<= 1) {
        int t = __shfl_up_sync(0xffffffffu, v, o);
        if (lane >= o) v += t;
    }
    __shared__ int wsum[32];
    if (lane == 31) wsum[wid] = v;
    __syncthreads();
    if (wid == 0) {
        int w = wsum[lane];
        #pragma unroll
        for (int o = 1; o < 32; o <<= 1) {
            int t = __shfl_up_sync(0xffffffffu, w, o);
            if (lane >= o) w += t;
        }
        wsum[lane] = w;
    }
    __syncthreads();
    int excl = v - sum + (wid ? wsum[wid - 1] : 0);

    int run = excl;
    for (int i = start; i < stop; i++) { g_off[i] = run; run += g_deg[i]; }
    if (tid == 1023) g_off[NN] = run;
}

// wvec_l = We_l @ ae_l, one warp per output element
__global__ void k_wvec(const float* __restrict__ We1, const float* __restrict__ ae1,
                       const float* __restrict__ We2, const float* __restrict__ ae2) {
    int gw = blockIdx.x * (blockDim.x >> 5) + (threadIdx.x >> 5);
    int lane = threadIdx.x & 31;
    if (gw >= 2 * ED) return;
    const float* We = (gw < ED) ? We1 : We2;
    const float* ae = (gw < ED) ? ae1 : ae2;
    int k = (gw < ED) ? gw : gw - ED;
    float s = We[k * HID + lane] * ae[lane] + We[k * HID + 32 + lane] * ae[32 + lane];
    #pragma unroll
    for (int o = 16; o > 0; o >>= 1) s += __shfl_xor_sync(0xffffffffu, s, o);
    if (lane == 0) {
        if (gw < ED) g_wvec1[k] = s; else g_wvec2[k] = s;
    }
}

// fill CSR + precompute hd1/hd2
__global__ void k_fill(const int* __restrict__ ei, const float* __restrict__ ea) {
    __shared__ float wv1[ED], wv2[ED];
    if (threadIdx.x < ED) wv1[threadIdx.x] = g_wvec1[threadIdx.x];
    else if (threadIdx.x < 2 * ED) wv2[threadIdx.x - ED] = g_wvec2[threadIdx.x - ED];
    __syncthreads();
    int e = blockIdx.x * blockDim.x + threadIdx.x;
    if (e >= NE) return;
    int src = ei[e], dst = ei[NE + e];
    const float4* ea4 = (const float4*)(ea + (size_t)e * ED);
    float h1 = 0.f, h2 = 0.f;
    #pragma unroll
    for (int i = 0; i < ED / 4; i++) {
        float4 v = ea4[i];
        float4 w1 = ((const float4*)wv1)[i];
        float4 w2 = ((const float4*)wv2)[i];
        h1 += v.x * w1.x + v.y * w1.y + v.z * w1.z + v.w * w1.w;
        h2 += v.x * w2.x + v.y * w2.y + v.z * w2.z + v.w * w2.w;
    }
    int pos = g_off[dst] + atomicAdd(&g_cnt[dst], 1);
    g_src_csr[pos] = src;
    g_hd1[pos] = h1;
    g_hd2[pos] = h2;
}

// ---------------- node GEMM (f32x2 outer-product): h = x@W, s_src, s_dst ----------------
// block: 64 nodes x 64 cols; thread (r,c) owns 4 nodes x 4 cols.
// smem: Ws[K][64] floats; xsT2[K][66] f32x2 (x transposed, lane-duplicated).
template <int K>
__global__ __launch_bounds__(256) void k_layer_gemm(
    const float* xext, const float* __restrict__ W,
    const float* __restrict__ avs, const float* __restrict__ avd, int use_internal)
{
    extern __shared__ char smraw[];
    float* Ws = (float*)smraw;                                        // K*64 floats
    unsigned long long* xsT2 = (unsigned long long*)(smraw + K * 64 * 4); // K*66
    const float* x = use_internal ? (const float*)g_x1 : xext;
    int tid = threadIdx.x;

    for (int i = tid; i < K * 16; i += 256) ((float4*)Ws)[i] = ((const float4*)W)[i];

    int base = blockIdx.x * 64;
    float4 z4 = make_float4(0.f, 0.f, 0.f, 0.f);
    for (int i4 = tid; i4 < 16 * K; i4 += 256) {     // 64 nodes * K/4 float4s
        int q = i4 & 3, m = (i4 >> 2) & 63, hi = i4 >> 8;
        int k4 = q + hi * 4;
        int n = base + m;
        float4 v = (n < NN) ? ((const float4*)(x + (size_t)n * K))[k4] : z4;
        int k = 4 * k4;
        xsT2[(k + 0) * 66 + m] = dup2(v.x);
        xsT2[(k + 1) * 66 + m] = dup2(v.y);
        xsT2[(k + 2) * 66 + m] = dup2(v.z);
        xsT2[(k + 3) * 66 + m] = dup2(v.w);
    }
    __syncthreads();

    int r = tid >> 4, c = tid & 15;
    unsigned long long acc[8] = {0, 0, 0, 0, 0, 0, 0, 0};  // [node i][col pair p]
    #pragma unroll 8
    for (int k = 0; k < K; k++) {
        ulonglong2 a01 = *(const ulonglong2*)&xsT2[k * 66 + 4 * r];
        ulonglong2 a23 = *(const ulonglong2*)&xsT2[k * 66 + 4 * r + 2];
        ulonglong2 w   = *(const ulonglong2*)&Ws[k * 64 + 4 * c];
        fma2(acc[0], a01.x, w.x); fma2(acc[1], a01.x, w.y);
        fma2(acc[2], a01.y, w.x); fma2(acc[3], a01.y, w.y);
        fma2(acc[4], a23.x, w.x); fma2(acc[5], a23.x, w.y);
        fma2(acc[6], a23.y, w.x); fma2(acc[7], a23.y, w.y);
    }

    float4 as4 = ((const float4*)avs)[c];
    float4 ad4 = ((const float4*)avd)[c];
    #pragma unroll
    for (int i = 0; i < 4; i++) {
        float2 p0 = unp(acc[i * 2]), p1 = unp(acc[i * 2 + 1]);
        float4 hv = make_float4(p0.x, p0.y, p1.x, p1.y);
        int n = base + 4 * r + i;
        float ps = hv.x * as4.x + hv.y * as4.y + hv.z * as4.z + hv.w * as4.w;
        float pd = hv.x * ad4.x + hv.y * ad4.y + hv.z * ad4.z + hv.w * ad4.w;
        #pragma unroll
        for (int o = 8; o > 0; o >>= 1) {
            ps += __shfl_down_sync(0xffffffffu, ps, o, 16);
            pd += __shfl_down_sync(0xffffffffu, pd, o, 16);
        }
        if (n < NN) {
            ((float4*)g_h)[n * 16 + c] = hv;
            if (c == 0) { g_ssrc[n] = ps; g_sdst[n] = pd; }
        }
    }
}

// ---------------- warp-per-node SINGLE-PASS softmax aggregation ----------------
__global__ __launch_bounds__(256) void k_agg(const float* __restrict__ hd,
                                             const float* __restrict__ bias,
                                             float* __restrict__ xout)
{
    int n = (blockIdx.x * blockDim.x + threadIdx.x) >> 5;
    int lane = threadIdx.x & 31;
    if (n >= NN) return;
    int beg = g_off[n];
    int end = g_off[n + 1];
    float sdst_n = g_sdst[n];

    float hds = 0.f, dl = 0.f;
    float accx = 0.f, accy = 0.f;   // lane owns cols {2*lane, 2*lane+1}

    for (int cb = beg; cb < end; cb += 32) {
        int j = cb + lane;
        bool valid = j < end;
        int sl = valid ? g_src_csr[j] : 0;
        float el = 0.f;
        if (valid) {
            float hdv = hd[j];
            hds += hdv;
            el = expf(lrelu(g_ssrc[sl] + sdst_n + hdv));
        }
        dl += el;
        int cnt = min(32, end - cb);
        #pragma unroll 4
        for (int k = 0; k < cnt; k++) {
            float ex = __shfl_sync(0xffffffffu, el, k);
            int s = __shfl_sync(0xffffffffu, sl, k);
            float2 hv = *(const float2*)&g_h[s * HID + 2 * lane];
            accx += ex * hv.x;
            accy += ex * hv.y;
        }
    }
    #pragma unroll
    for (int o = 16; o > 0; o >>= 1) {
        hds += __shfl_xor_sync(0xffffffffu, hds, o);
        dl  += __shfl_xor_sync(0xffffffffu, dl, o);
    }
    int deg = end - beg;
    float ld = hds / fmaxf((float)deg, 1.f);
    float exl = expf(lrelu(g_ssrc[n] + sdst_n + ld));
    dl += exl;
    float2 hn = *(const float2*)&g_h[n * HID + 2 * lane];
    accx += exl * hn.x;
    accy += exl * hn.y;

    float inv = 1.f / dl;
    float2 b2v = *(const float2*)&bias[2 * lane];
    float2 o;
    o.x = fmaxf(accx * inv + b2v.x, 0.f);
    o.y = fmaxf(accy * inv + b2v.y, 0.f);
    *(float2*)&xout[n * HID + 2 * lane] = o;
}

// ---------------- p/q dual GEMM (f32x2): p = x2@Wp+bc1, q = x2@Wq ----------------
__global__ __launch_bounds__(256) void k_pq(const float* __restrict__ Wc1,
                                            const float* __restrict__ bc1)
{
    extern __shared__ char smraw[];
    float* Ws = (float*)smraw;                                         // [64][128]
    unsigned long long* xsT2 = (unsigned long long*)(smraw + 64 * 128 * 4); // [64][66]
    int tid = threadIdx.x;

    // Ws[k][0:64] = Wp[k] (Wc1 rows 0..63), Ws[k][64:128] = Wq[k] (rows 64..127)
    for (int i4 = tid; i4 < 2048; i4 += 256) {
        int k = i4 >> 5, j4 = i4 & 31;
        float4 v = (j4 < 16) ? ((const float4*)Wc1)[k * 16 + j4]
                             : ((const float4*)Wc1)[(64 + k) * 16 + (j4 - 16)];
        ((float4*)Ws)[k * 32 + j4] = v;
    }

    int base = blockIdx.x * 64;
    float4 z4 = make_float4(0.f, 0.f, 0.f, 0.f);
    for (int i4 = tid; i4 < 1024; i4 += 256) {
        int q = i4 & 3, m = (i4 >> 2) & 63, hi = i4 >> 8;
        int k4 = q + hi * 4;
        int n = base + m;
        float4 v = (n < NN) ? ((const float4*)(g_x2 + (size_t)n * 64))[k4] : z4;
        int k = 4 * k4;
        xsT2[(k + 0) * 66 + m] = dup2(v.x);
        xsT2[(k + 1) * 66 + m] = dup2(v.y);
        xsT2[(k + 2) * 66 + m] = dup2(v.z);
        xsT2[(k + 3) * 66 + m] = dup2(v.w);
    }
    __syncthreads();

    int r = tid >> 4, c = tid & 15;
    unsigned long long accP[8] = {0, 0, 0, 0, 0, 0, 0, 0};
    unsigned long long accQ[8] = {0, 0, 0, 0, 0, 0, 0, 0};
    #pragma unroll 8
    for (int k = 0; k < 64; k++) {
        ulonglong2 a01 = *(const ulonglong2*)&xsT2[k * 66 + 4 * r];
        ulonglong2 a23 = *(const ulonglong2*)&xsT2[k * 66 + 4 * r + 2];
        ulonglong2 wp  = *(const ulonglong2*)&Ws[k * 128 + 4 * c];
        ulonglong2 wq  = *(const ulonglong2*)&Ws[k * 128 + 64 + 4 * c];
        fma2(accP[0], a01.x, wp.x); fma2(accP[1], a01.x, wp.y);
        fma2(accP[2], a01.y, wp.x); fma2(accP[3], a01.y, wp.y);
        fma2(accP[4], a23.x, wp.x); fma2(accP[5], a23.x, wp.y);
        fma2(accP[6], a23.y, wp.x); fma2(accP[7], a23.y, wp.y);
        fma2(accQ[0], a01.x, wq.x); fma2(accQ[1], a01.x, wq.y);
        fma2(accQ[2], a01.y, wq.x); fma2(accQ[3], a01.y, wq.y);
        fma2(accQ[4], a23.x, wq.x); fma2(accQ[5], a23.x, wq.y);
        fma2(accQ[6], a23.y, wq.x); fma2(accQ[7], a23.y, wq.y);
    }

    float4 b4 = ((const float4*)bc1)[c];
    #pragma unroll
    for (int i = 0; i < 4; i++) {
        int n = base + 4 * r + i;
        if (n >= NN) continue;
        float2 p0 = unp(accP[i * 2]), p1 = unp(accP[i * 2 + 1]);
        float2 q0 = unp(accQ[i * 2]), q1 = unp(accQ[i * 2 + 1]);
        ((float4*)g_p)[n * 16 + c] = make_float4(p0.x + b4.x, p0.y + b4.y,
                                                 p1.x + b4.z, p1.y + b4.w);
        ((float4*)g_q)[n * 16 + c] = make_float4(q0.x, q0.y, q1.x, q1.y);
    }
}

// ---------------- final edge MLP: 2 threads/edge, f32x2 register-blocked ----------------
__global__ __launch_bounds__(256) void k_final(
    const int* __restrict__ ei, const float* __restrict__ ea,
    const float* __restrict__ Wc1, const float* __restrict__ Wc2,
    const float* __restrict__ bc2, float* __restrict__ out)
{
    __shared__ float Ws[ED * HID];   // Wc1 rows 128..159: [32][64]
    __shared__ float wc2s[HID];
    int tid = threadIdx.x;
    for (int i = tid; i < ED * HID; i += 256) Ws[i] = Wc1[2 * HID * HID + i];
    if (tid < HID) wc2s[tid] = Wc2[tid];
    __syncthreads();

    int t = blockIdx.x * 256 + tid;
    int e = t >> 1;
    int half = t & 1;
    if (e >= NE) return;
    int src = ei[e], dst = ei[NE + e];

    float4 A[8];
    const float4* ea4 = (const float4*)(ea + (size_t)e * ED);
    #pragma unroll
    for (int i = 0; i < 8; i++) A[i] = ea4[i];
    const float* a = (const float*)A;

    unsigned long long acc[16];
    #pragma unroll
    for (int j = 0; j < 16; j++) acc[j] = 0ull;

    #pragma unroll
    for (int k = 0; k < ED; k++) {
        unsigned long long ak = dup2(a[k]);
        const ulonglong2* wrow = (const ulonglong2*)&Ws[k * HID + half * 32];
        #pragma unroll
        for (int j = 0; j < 8; j++) {
            ulonglong2 w = wrow[j];
            fma2(acc[2 * j], ak, w.x);
            fma2(acc[2 * j + 1], ak, w.y);
        }
    }

    const float4* p4 = (const float4*)&g_p[src * HID + half * 32];
    const float4* q4 = (const float4*)&g_q[dst * HID + half * 32];
    const float4* w4 = (const float4*)&wc2s[half * 32];
    float s = 0.f;
    #pragma unroll
    for (int j = 0; j < 8; j++) {
        float2 a0 = unp(acc[2 * j]);
        float2 a1 = unp(acc[2 * j + 1]);
        float4 pv = p4[j], qv = q4[j], wv = w4[j];
        float hx = fmaxf(pv.x + qv.x + a0.x, 0.f);
        float hy = fmaxf(pv.y + qv.y + a0.y, 0.f);
        float hz = fmaxf(pv.z + qv.z + a1.x, 0.f);
        float hw = fmaxf(pv.w + qv.w + a1.y, 0.f);
        s += hx * wv.x + hy * wv.y + hz * wv.z + hw * wv.w;
    }
    s += __shfl_down_sync(0xffffffffu, s, 1);
    if (half == 0) out[e] = s + bc2[0];
}

// ---------------- launch sequence ----------------
extern "C" void kernel_launch(void* const* d_in, const int* in_sizes, int n_in,
                              void* d_out, int out_size)
{
    const float* x   = (const float*)d_in[0];
    const int*   ei  = (const int*)d_in[1];
    const float* ea  = (const float*)d_in[2];
    const float* W1  = (const float*)d_in[3];
    const float* We1 = (const float*)d_in[4];
    const float* as1 = (const float*)d_in[5];
    const float* ad1 = (const float*)d_in[6];
    const float* ae1 = (const float*)d_in[7];
    const float* b1  = (const float*)d_in[8];
    const float* W2  = (const float*)d_in[9];
    const float* We2 = (const float*)d_in[10];
    const float* as2 = (const float*)d_in[11];
    const float* ad2 = (const float*)d_in[12];
    const float* ae2 = (const float*)d_in[13];
    const float* b2  = (const float*)d_in[14];
    const float* Wc1 = (const float*)d_in[15];
    const float* bc1 = (const float*)d_in[16];
    const float* Wc2 = (const float*)d_in[17];
    const float* bc2 = (const float*)d_in[18];
    float* out = (float*)d_out;

    const int TB = 256;
    const int NB_N   = (NN + TB - 1) / TB;
    const int NB_E   = (NE + TB - 1) / TB;
    const int NB_AGG = (NN * 32 + TB - 1) / TB;
    const int NB_FIN = (NE * 2 + TB - 1) / TB;
    const int NB_TILE = (NN + 63) / 64;              // 782, one 64-node tile per block

    const int SM_G128 = IN_DIM * 64 * 4 + IN_DIM * 66 * 8;  // 100352
    const int SM_G64  = HID * 64 * 4 + HID * 66 * 8;        // 50176
    const int SM_PQ   = 64 * 128 * 4 + 64 * 66 * 8;         // 66560

    cudaFuncSetAttribute(k_layer_gemm<IN_DIM>, cudaFuncAttributeMaxDynamicSharedMemorySize, SM_G128);
    cudaFuncSetAttribute(k_layer_gemm<HID>,    cudaFuncAttributeMaxDynamicSharedMemorySize, SM_G64);
    cudaFuncSetAttribute(k_pq,                 cudaFuncAttributeMaxDynamicSharedMemorySize, SM_PQ);

    float* g_x1p; cudaGetSymbolAddress((void**)&g_x1p, g_x1);
    float* g_x2p; cudaGetSymbolAddress((void**)&g_x2p, g_x2);
    float* g_hd1p; cudaGetSymbolAddress((void**)&g_hd1p, g_hd1);
    float* g_hd2p; cudaGetSymbolAddress((void**)&g_hd2p, g_hd2);

    // 4th launch = layer-1 GEMM (ncu capture slot): verify f32x2 prediction
    k_zero<<<NB_N, TB>>>();                                             // 1
    k_count_deg<<<NB_E, TB>>>(ei);                                      // 2
    k_wvec<<<2, 1024>>>(We1, ae1, We2, ae2);                            // 3
    k_layer_gemm<IN_DIM><<<NB_TILE, TB, SM_G128>>>(x, W1, as1, ad1, 0); // 4 <- profiled
    k_scan<<<1, 1024>>>();                                              // 5
    k_fill<<<NB_E, TB>>>(ei, ea);                                       // 6

    k_agg<<<NB_AGG, TB>>>(g_hd1p, b1, g_x1p);                           // 7

    k_layer_gemm<HID><<<NB_TILE, TB, SM_G64>>>(x, W2, as2, ad2, 1);     // 8
    k_agg<<<NB_AGG, TB>>>(g_hd2p, b2, g_x2p);                           // 9

    k_pq<<<NB_TILE, TB, SM_PQ>>>(Wc1, bc1);                             // 10
    k_final<<<NB_FIN, TB>>>(ei, ea, Wc1, Wc2, bc2, out);                // 11
}

// round 9
// speedup vs baseline: 1.2380x; 1.2380x over previous
#include <cuda_runtime.h>
#include <math.h>
#include <stdint.h>

#define NN 50000
#define NE 800000
#define HID 64
#define IN_DIM 128
#define ED 32
#define NEG 0.2f

// ---------------- device scratch ----------------
__device__ __align__(16) float g_h[NN * HID];     // current layer node transform
__device__ __align__(16) float g_x1[NN * HID];    // layer-1 output
__device__ __align__(16) float g_x2[NN * HID];    // layer-2 output
__device__ __align__(16) float g_p[NN * HID];     // x2 @ Wc1[0:64] + bc1
__device__ __align__(16) float g_q[NN * HID];     // x2 @ Wc1[64:128]
__device__ float g_ssrc[NN];
__device__ float g_sdst[NN];
__device__ int g_deg[NN];
__device__ int g_cnt[NN];
__device__ int g_off[NN + 1];
__device__ int g_src_csr[NE];
__device__ float g_hd1[NE];                       // ea . wvec1, CSR order
__device__ float g_hd2[NE];                       // ea . wvec2, CSR order
__device__ float g_wvec1[ED];
__device__ float g_wvec2[ED];

__device__ __forceinline__ float lrelu(float x) { return x > 0.f ? x : NEG * x; }

// ---- packed fp32x2 helpers (Blackwell FFMA2: 2x fp32 FMA per issue slot) ----
__device__ __forceinline__ void fma2(unsigned long long& d, unsigned long long a,
                                     unsigned long long b) {
    asm("fma.rn.f32x2 %0, %1, %2, %0;" : "+l"(d) : "l"(a), "l"(b));
}
__device__ __forceinline__ unsigned long long dup2(float v) {
    unsigned long long d;
    unsigned u = __float_as_uint(v);
    asm("mov.b64 %0, {%1, %1};" : "=l"(d) : "r"(u));
    return d;
}
__device__ __forceinline__ float2 unp(unsigned long long v) {
    unsigned lo, hi;
    asm("mov.b64 {%0, %1}, %2;" : "=r"(lo), "=r"(hi) : "l"(v));
    return make_float2(__uint_as_float(lo), __uint_as_float(hi));
}

// ---------------- CSR build ----------------
__global__ void k_zero() {
    int n = blockIdx.x * blockDim.x + threadIdx.x;
    if (n < NN) { g_deg[n] = 0; g_cnt[n] = 0; }
}

__global__ void k_count_deg(const int* __restrict__ ei) {
    int e = blockIdx.x * blockDim.x + threadIdx.x;
    if (e < NE) atomicAdd(&g_deg[ei[NE + e]], 1);
}

// fast single-block exclusive scan
__global__ __launch_bounds__(1024) void k_scan() {
    const int PER = (NN + 1023) / 1024;   // 49
    int tid = threadIdx.x;
    int lane = tid & 31, wid = tid >> 5;
    int start = tid * PER;
    int stop = min(start + PER, NN);

    int sum = 0;
    for (int i = start; i < stop; i++) sum += g_deg[i];

    int v = sum;
    #pragma unroll
    for (int o = 1; o < 32; o <<= 1) {
        int t = __shfl_up_sync(0xffffffffu, v, o);
        if (lane >= o) v += t;
    }
    __shared__ int wsum[32];
    if (lane == 31) wsum[wid] = v;
    __syncthreads();
    if (wid == 0) {
        int w = wsum[lane];
        #pragma unroll
        for (int o = 1; o < 32; o <<= 1) {
            int t = __shfl_up_sync(0xffffffffu, w, o);
            if (lane >= o) w += t;
        }
        wsum[lane] = w;
    }
    __syncthreads();
    int excl = v - sum + (wid ? wsum[wid - 1] : 0);

    int run = excl;
    for (int i = start; i < stop; i++) { g_off[i] = run; run += g_deg[i]; }
    if (tid == 1023) g_off[NN] = run;
}

// wvec_l = We_l @ ae_l, one warp per output element
__global__ void k_wvec(const float* __restrict__ We1, const float* __restrict__ ae1,
                       const float* __restrict__ We2, const float* __restrict__ ae2) {
    int gw = blockIdx.x * (blockDim.x >> 5) + (threadIdx.x >> 5);
    int lane = threadIdx.x & 31;
    if (gw >= 2 * ED) return;
    const float* We = (gw < ED) ? We1 : We2;
    const float* ae = (gw < ED) ? ae1 : ae2;
    int k = (gw < ED) ? gw : gw - ED;
    float s = We[k * HID + lane] * ae[lane] + We[k * HID + 32 + lane] * ae[32 + lane];
    #pragma unroll
    for (int o = 16; o > 0; o >>= 1) s += __shfl_xor_sync(0xffffffffu, s, o);
    if (lane == 0) {
        if (gw < ED) g_wvec1[k] = s; else g_wvec2[k] = s;
    }
}

// fill CSR + precompute hd1/hd2
__global__ void k_fill(const int* __restrict__ ei, const float* __restrict__ ea) {
    __shared__ float wv1[ED], wv2[ED];
    if (threadIdx.x < ED) wv1[threadIdx.x] = g_wvec1[threadIdx.x];
    else if (threadIdx.x < 2 * ED) wv2[threadIdx.x - ED] = g_wvec2[threadIdx.x - ED];
    __syncthreads();
    int e = blockIdx.x * blockDim.x + threadIdx.x;
    if (e >= NE) return;
    int src = ei[e], dst = ei[NE + e];
    const float4* ea4 = (const float4*)(ea + (size_t)e * ED);
    float h1 = 0.f, h2 = 0.f;
    #pragma unroll
    for (int i = 0; i < ED / 4; i++) {
        float4 v = ea4[i];
        float4 w1 = ((const float4*)wv1)[i];
        float4 w2 = ((const float4*)wv2)[i];
        h1 += v.x * w1.x + v.y * w1.y + v.z * w1.z + v.w * w1.w;
        h2 += v.x * w2.x + v.y * w2.y + v.z * w2.z + v.w * w2.w;
    }
    int pos = g_off[dst] + atomicAdd(&g_cnt[dst], 1);
    g_src_csr[pos] = src;
    g_hd1[pos] = h1;
    g_hd2[pos] = h2;
}

// ---------------- node GEMM: h = x@W, s_src, s_dst ----------------
// Tile: 32 nodes x 64 cols. Thread (r=tid>>3, c=tid&7) owns node r, cols [8c, 8c+8).
// Per k: 1 scalar LDS (x bcast) + dup + 2 LDS.128 (W) + 4 FFMA2.
// smem: Ws[K][64] + xs[32][K+4] (pad kills bank conflicts on the scalar read).
template <int K>
__global__ __launch_bounds__(256) void k_layer_gemm(
    const float* xext, const float* __restrict__ W,
    const float* __restrict__ avs, const float* __restrict__ avd, int use_internal)
{
    extern __shared__ char smraw[];
    float* Ws = (float*)smraw;                       // K*64 floats
    float* xs = (float*)(smraw + K * 64 * 4);        // 32*(K+4) floats
    const int XST = K + 4;
    const float* x = use_internal ? (const float*)g_x1 : xext;
    int tid = threadIdx.x;

    for (int i = tid; i < K * 16; i += 256) ((float4*)Ws)[i] = ((const float4*)W)[i];

    int base = blockIdx.x * 32;
    float4 z4 = make_float4(0.f, 0.f, 0.f, 0.f);
    for (int i = tid; i < 8 * K; i += 256) {         // 32 rows * K/4 float4
        int m = i / (K / 4), k4 = i % (K / 4);
        int n = base + m;
        float4 v = (n < NN) ? ((const float4*)(x + (size_t)n * K))[k4] : z4;
        *(float4*)&xs[m * XST + 4 * k4] = v;
    }
    __syncthreads();

    int r = tid >> 3, c = tid & 7;
    unsigned long long acc[4] = {0, 0, 0, 0};        // cols 8c..8c+7 as 4 pairs
    const float* xr = &xs[r * XST];
    const ulonglong2* Wp2 = (const ulonglong2*)Ws;   // row k = 16 ulonglong2
    #pragma unroll 8
    for (int k = 0; k < K; k++) {
        unsigned long long xv = dup2(xr[k]);
        ulonglong2 w0 = Wp2[k * 16 + 2 * c];
        ulonglong2 w1 = Wp2[k * 16 + 2 * c + 1];
        fma2(acc[0], xv, w0.x); fma2(acc[1], xv, w0.y);
        fma2(acc[2], xv, w1.x); fma2(acc[3], xv, w1.y);
    }

    float2 u0 = unp(acc[0]), u1 = unp(acc[1]), u2 = unp(acc[2]), u3 = unp(acc[3]);
    float4 h0 = make_float4(u0.x, u0.y, u1.x, u1.y);
    float4 h1 = make_float4(u2.x, u2.y, u3.x, u3.y);
    float4 asa = ((const float4*)avs)[2 * c], asb = ((const float4*)avs)[2 * c + 1];
    float4 ada = ((const float4*)avd)[2 * c], adb = ((const float4*)avd)[2 * c + 1];
    float ps = h0.x * asa.x + h0.y * asa.y + h0.z * asa.z + h0.w * asa.w
             + h1.x * asb.x + h1.y * asb.y + h1.z * asb.z + h1.w * asb.w;
    float pd = h0.x * ada.x + h0.y * ada.y + h0.z * ada.z + h0.w * ada.w
             + h1.x * adb.x + h1.y * adb.y + h1.z * adb.z + h1.w * adb.w;
    #pragma unroll
    for (int o = 4; o > 0; o >>= 1) {
        ps += __shfl_down_sync(0xffffffffu, ps, o, 8);
        pd += __shfl_down_sync(0xffffffffu, pd, o, 8);
    }
    int n = base + r;
    if (n < NN) {
        ((float4*)g_h)[n * 16 + 2 * c] = h0;
        ((float4*)g_h)[n * 16 + 2 * c + 1] = h1;
        if (c == 0) { g_ssrc[n] = ps; g_sdst[n] = pd; }
    }
}

// ---------------- warp-per-node SINGLE-PASS softmax aggregation ----------------
__global__ __launch_bounds__(256) void k_agg(const float* __restrict__ hd,
                                             const float* __restrict__ bias,
                                             float* __restrict__ xout)
{
    int n = (blockIdx.x * blockDim.x + threadIdx.x) >> 5;
    int lane = threadIdx.x & 31;
    if (n >= NN) return;
    int beg = g_off[n];
    int end = g_off[n + 1];
    float sdst_n = g_sdst[n];

    float hds = 0.f, dl = 0.f;
    float accx = 0.f, accy = 0.f;   // lane owns cols {2*lane, 2*lane+1}

    for (int cb = beg; cb < end; cb += 32) {
        int j = cb + lane;
        bool valid = j < end;
        int sl = valid ? g_src_csr[j] : 0;
        float el = 0.f;
        if (valid) {
            float hdv = hd[j];
            hds += hdv;
            el = expf(lrelu(g_ssrc[sl] + sdst_n + hdv));
        }
        dl += el;
        int cnt = min(32, end - cb);
        #pragma unroll 4
        for (int k = 0; k < cnt; k++) {
            float ex = __shfl_sync(0xffffffffu, el, k);
            int s = __shfl_sync(0xffffffffu, sl, k);
            float2 hv = *(const float2*)&g_h[s * HID + 2 * lane];
            accx += ex * hv.x;
            accy += ex * hv.y;
        }
    }
    #pragma unroll
    for (int o = 16; o > 0; o >>= 1) {
        hds += __shfl_xor_sync(0xffffffffu, hds, o);
        dl  += __shfl_xor_sync(0xffffffffu, dl, o);
    }
    int deg = end - beg;
    float ld = hds / fmaxf((float)deg, 1.f);
    float exl = expf(lrelu(g_ssrc[n] + sdst_n + ld));
    dl += exl;
    float2 hn = *(const float2*)&g_h[n * HID + 2 * lane];
    accx += exl * hn.x;
    accy += exl * hn.y;

    float inv = 1.f / dl;
    float2 b2v = *(const float2*)&bias[2 * lane];
    float2 o;
    o.x = fmaxf(accx * inv + b2v.x, 0.f);
    o.y = fmaxf(accy * inv + b2v.y, 0.f);
    *(float2*)&xout[n * HID + 2 * lane] = o;
}

// ---------------- p/q dual GEMM: p = x2@Wp+bc1, q = x2@Wq ----------------
// Same tiling as k_layer_gemm; thread owns 8 P-cols and 8 Q-cols.
__global__ __launch_bounds__(256) void k_pq(const float* __restrict__ Wc1,
                                            const float* __restrict__ bc1)
{
    extern __shared__ char smraw[];
    float* Ws = (float*)smraw;                        // [64][128]: row k = Wp[k] | Wq[k]
    float* xs = (float*)(smraw + 64 * 128 * 4);       // [32][68]
    const int XST = 68;
    int tid = threadIdx.x;

    for (int i4 = tid; i4 < 2048; i4 += 256) {
        int k = i4 >> 5, j4 = i4 & 31;
        float4 v = (j4 < 16) ? ((const float4*)Wc1)[k * 16 + j4]
                             : ((const float4*)Wc1)[(64 + k) * 16 + (j4 - 16)];
        ((float4*)Ws)[k * 32 + j4] = v;
    }

    int base = blockIdx.x * 32;
    float4 z4 = make_float4(0.f, 0.f, 0.f, 0.f);
    for (int i = tid; i < 512; i += 256) {            // 32 rows * 16 float4
        int m = i >> 4, k4 = i & 15;
        int n = base + m;
        float4 v = (n < NN) ? ((const float4*)(g_x2 + (size_t)n * 64))[k4] : z4;
        *(float4*)&xs[m * XST + 4 * k4] = v;
    }
    __syncthreads();

    int r = tid >> 3, c = tid & 7;
    unsigned long long accP[4] = {0, 0, 0, 0};
    unsigned long long accQ[4] = {0, 0, 0, 0};
    const float* xr = &xs[r * XST];
    const ulonglong2* Wp2 = (const ulonglong2*)Ws;    // row k = 32 ulonglong2
    #pragma unroll 8
    for (int k = 0; k < 64; k++) {
        unsigned long long xv = dup2(xr[k]);
        ulonglong2 p0 = Wp2[k * 32 + 2 * c];
        ulonglong2 p1 = Wp2[k * 32 + 2 * c + 1];
        ulonglong2 q0 = Wp2[k * 32 + 16 + 2 * c];
        ulonglong2 q1 = Wp2[k * 32 + 16 + 2 * c + 1];
        fma2(accP[0], xv, p0.x); fma2(accP[1], xv, p0.y);
        fma2(accP[2], xv, p1.x); fma2(accP[3], xv, p1.y);
        fma2(accQ[0], xv, q0.x); fma2(accQ[1], xv, q0.y);
        fma2(accQ[2], xv, q1.x); fma2(accQ[3], xv, q1.y);
    }

    int n = base + r;
    if (n >= NN) return;
    float4 ba = ((const float4*)bc1)[2 * c], bb = ((const float4*)bc1)[2 * c + 1];
    float2 p0 = unp(accP[0]), p1 = unp(accP[1]), p2 = unp(accP[2]), p3 = unp(accP[3]);
    float2 q0 = unp(accQ[0]), q1 = unp(accQ[1]), q2 = unp(accQ[2]), q3 = unp(accQ[3]);
    ((float4*)g_p)[n * 16 + 2 * c]     = make_float4(p0.x + ba.x, p0.y + ba.y, p1.x + ba.z, p1.y + ba.w);
    ((float4*)g_p)[n * 16 + 2 * c + 1] = make_float4(p2.x + bb.x, p2.y + bb.y, p3.x + bb.z, p3.y + bb.w);
    ((float4*)g_q)[n * 16 + 2 * c]     = make_float4(q0.x, q0.y, q1.x, q1.y);
    ((float4*)g_q)[n * 16 + 2 * c + 1] = make_float4(q2.x, q2.y, q3.x, q3.y);
}

// ---------------- final edge MLP: 2 threads per edge, register-blocked ----------------
__global__ __launch_bounds__(256) void k_final(
    const int* __restrict__ ei, const float* __restrict__ ea,
    const float* __restrict__ Wc1, const float* __restrict__ Wc2,
    const float* __restrict__ bc2, float* __restrict__ out)
{
    __shared__ float Ws[ED * HID];   // Wc1 rows 128..159: [32][64]
    __shared__ float wc2s[HID];
    int tid = threadIdx.x;
    for (int i = tid; i < ED * HID; i += 256) Ws[i] = Wc1[2 * HID * HID + i];
    if (tid < HID) wc2s[tid] = Wc2[tid];
    __syncthreads();

    int t = blockIdx.x * 256 + tid;
    int e = t >> 1;
    int half = t & 1;
    if (e >= NE) return;
    int src = ei[e], dst = ei[NE + e];

    float4 A[8];
    const float4* ea4 = (const float4*)(ea + (size_t)e * ED);
    #pragma unroll
    for (int i = 0; i < 8; i++) A[i] = ea4[i];
    const float* a = (const float*)A;

    float4 acc[8];
    #pragma unroll
    for (int j = 0; j < 8; j++) acc[j] = make_float4(0.f, 0.f, 0.f, 0.f);

    const float4* Ws4 = (const float4*)Ws;
    #pragma unroll
    for (int k = 0; k < ED; k++) {
        float ak = a[k];
        #pragma unroll
        for (int j = 0; j < 8; j++) {
            float4 w = Ws4[k * 16 + half * 8 + j];
            acc[j].x += ak * w.x; acc[j].y += ak * w.y;
            acc[j].z += ak * w.z; acc[j].w += ak * w.w;
        }
    }

    const float4* p4 = (const float4*)&g_p[src * HID + half * 32];
    const float4* q4 = (const float4*)&g_q[dst * HID + half * 32];
    const float4* w4 = (const float4*)&wc2s[half * 32];
    float s = 0.f;
    #pragma unroll
    for (int j = 0; j < 8; j++) {
        float4 pv = p4[j], qv = q4[j], wv = w4[j];
        float hx = fmaxf(pv.x + qv.x + acc[j].x, 0.f);
        float hy = fmaxf(pv.y + qv.y + acc[j].y, 0.f);
        float hz = fmaxf(pv.z + qv.z + acc[j].z, 0.f);
        float hw = fmaxf(pv.w + qv.w + acc[j].w, 0.f);
        s += hx * wv.x + hy * wv.y + hz * wv.z + hw * wv.w;
    }
    s += __shfl_down_sync(0xffffffffu, s, 1);
    if (half == 0) out[e] = s + bc2[0];
}

// ---------------- launch sequence ----------------
extern "C" void kernel_launch(void* const* d_in, const int* in_sizes, int n_in,
                              void* d_out, int out_size)
{
    const float* x   = (const float*)d_in[0];
    const int*   ei  = (const int*)d_in[1];
    const float* ea  = (const float*)d_in[2];
    const float* W1  = (const float*)d_in[3];
    const float* We1 = (const float*)d_in[4];
    const float* as1 = (const float*)d_in[5];
    const float* ad1 = (const float*)d_in[6];
    const float* ae1 = (const float*)d_in[7];
    const float* b1  = (const float*)d_in[8];
    const float* W2  = (const float*)d_in[9];
    const float* We2 = (const float*)d_in[10];
    const float* as2 = (const float*)d_in[11];
    const float* ad2 = (const float*)d_in[12];
    const float* ae2 = (const float*)d_in[13];
    const float* b2  = (const float*)d_in[14];
    const float* Wc1 = (const float*)d_in[15];
    const float* bc1 = (const float*)d_in[16];
    const float* Wc2 = (const float*)d_in[17];
    const float* bc2 = (const float*)d_in[18];
    float* out = (float*)d_out;

    const int TB = 256;
    const int NB_N   = (NN + TB - 1) / TB;
    const int NB_E   = (NE + TB - 1) / TB;
    const int NB_AGG = (NN * 32 + TB - 1) / TB;
    const int NB_FIN = (NE * 2 + TB - 1) / TB;
    const int NB_T32 = (NN + 31) / 32;               // 1563: one 32-node tile per block

    const int SM_G128 = IN_DIM * 64 * 4 + 32 * (IN_DIM + 4) * 4;  // 32768+16896 = 49664
    const int SM_G64  = HID * 64 * 4 + 32 * (HID + 4) * 4;        // 16384+8704  = 25088
    const int SM_PQ   = 64 * 128 * 4 + 32 * 68 * 4;               // 32768+8704  = 41472

    cudaFuncSetAttribute(k_layer_gemm<IN_DIM>, cudaFuncAttributeMaxDynamicSharedMemorySize, SM_G128);
    cudaFuncSetAttribute(k_layer_gemm<HID>,    cudaFuncAttributeMaxDynamicSharedMemorySize, SM_G64);
    cudaFuncSetAttribute(k_pq,                 cudaFuncAttributeMaxDynamicSharedMemorySize, SM_PQ);

    float* g_x1p; cudaGetSymbolAddress((void**)&g_x1p, g_x1);
    float* g_x2p; cudaGetSymbolAddress((void**)&g_x2p, g_x2);
    float* g_hd1p; cudaGetSymbolAddress((void**)&g_hd1p, g_hd1);
    float* g_hd2p; cudaGetSymbolAddress((void**)&g_hd2p, g_hd2);

    // 4th launch = layer-1 GEMM (ncu capture slot)
    k_zero<<<NB_N, TB>>>();                                             // 1
    k_count_deg<<<NB_E, TB>>>(ei);                                      // 2
    k_wvec<<<2, 1024>>>(We1, ae1, We2, ae2);                            // 3
    k_layer_gemm<IN_DIM><<<NB_T32, TB, SM_G128>>>(x, W1, as1, ad1, 0);  // 4 <- profiled
    k_scan<<<1, 1024>>>();                                              // 5
    k_fill<<<NB_E, TB>>>(ei, ea);                                       // 6

    k_agg<<<NB_AGG, TB>>>(g_hd1p, b1, g_x1p);                           // 7

    k_layer_gemm<HID><<<NB_T32, TB, SM_G64>>>(x, W2, as2, ad2, 1);      // 8
    k_agg<<<NB_AGG, TB>>>(g_hd2p, b2, g_x2p);                           // 9

    k_pq<<<NB_T32, TB, SM_PQ>>>(Wc1, bc1);                              // 10
    k_final<<<NB_FIN, TB>>>(ei, ea, Wc1, Wc2, bc2, out);                // 11
}

// round 10
// speedup vs baseline: 1.6547x; 1.3366x over previous
#include <cuda_runtime.h>
#include <math.h>
#include <stdint.h>

#define NN 50000
#define NE 800000
#define HID 64
#define IN_DIM 128
#define ED 32
#define NEG 0.2f

// ---------------- device scratch ----------------
__device__ __align__(16) float g_h[NN * HID];     // current layer node transform
__device__ __align__(16) float g_x1[NN * HID];    // layer-1 output
__device__ __align__(16) float g_x2[NN * HID];    // layer-2 output
__device__ __align__(16) float g_p[NN * HID];     // x2 @ Wc1[0:64] + bc1
__device__ __align__(16) float g_q[NN * HID];     // x2 @ Wc1[64:128]
__device__ float g_ssrc[NN];
__device__ float g_sdst[NN];
__device__ int g_deg[NN];
__device__ int g_cnt[NN];
__device__ int g_off[NN + 1];
__device__ int g_src_csr[NE];
__device__ float g_hd1[NE];                       // ea . wvec1, CSR order
__device__ float g_hd2[NE];                       // ea . wvec2, CSR order
__device__ float g_wvec1[ED];
__device__ float g_wvec2[ED];

__device__ __forceinline__ float lrelu(float x) { return x > 0.f ? x : NEG * x; }

// ---- packed fp32x2 helpers ----
__device__ __forceinline__ void fma2(unsigned long long& d, unsigned long long a,
                                     unsigned long long b) {
    asm("fma.rn.f32x2 %0, %1, %2, %0;" : "+l"(d) : "l"(a), "l"(b));
}
__device__ __forceinline__ unsigned long long dup2(float v) {
    unsigned long long d;
    unsigned u = __float_as_uint(v);
    asm("mov.b64 %0, {%1, %1};" : "=l"(d) : "r"(u));
    return d;
}
__device__ __forceinline__ float2 unp(unsigned long long v) {
    unsigned lo, hi;
    asm("mov.b64 {%0, %1}, %2;" : "=r"(lo), "=r"(hi) : "l"(v));
    return make_float2(__uint_as_float(lo), __uint_as_float(hi));
}

// ---------------- fused zero + wvec (frees the ncu capture slot for k_fill) ----------------
__global__ void k_zw(const float* __restrict__ We1, const float* __restrict__ ae1,
                     const float* __restrict__ We2, const float* __restrict__ ae2) {
    int b = blockIdx.x;
    if (b < 196) {
        int n = b * 256 + threadIdx.x;
        if (n < NN) { g_deg[n] = 0; g_cnt[n] = 0; }
    } else {
        int t = threadIdx.x;
        int o = t >> 2;          // 0..63 output index
        int q = t & 3;
        const float* We = (o < ED) ? We1 : We2;
        const float* ae = (o < ED) ? ae1 : ae2;
        int k = (o < ED) ? o : o - ED;
        float s = 0.f;
        for (int j = q; j < HID; j += 4) s += We[k * HID + j] * ae[j];
        s += __shfl_down_sync(0xffffffffu, s, 2, 4);
        s += __shfl_down_sync(0xffffffffu, s, 1, 4);
        if (q == 0) {
            if (o < ED) g_wvec1[o] = s; else g_wvec2[o - ED] = s;
        }
    }
}

__global__ void k_count_deg(const int* __restrict__ ei) {
    int e = blockIdx.x * blockDim.x + threadIdx.x;
    if (e < NE) atomicAdd(&g_deg[ei[NE + e]], 1);
}

// fast single-block exclusive scan
__global__ __launch_bounds__(1024) void k_scan() {
    const int PER = (NN + 1023) / 1024;   // 49
    int tid = threadIdx.x;
    int lane = tid & 31, wid = tid >> 5;
    int start = tid * PER;
    int stop = min(start + PER, NN);

    int sum = 0;
    for (int i = start; i < stop; i++) sum += g_deg[i];

    int v = sum;
    #pragma unroll
    for (int o = 1; o < 32; o <<= 1) {
        int t = __shfl_up_sync(0xffffffffu, v, o);
        if (lane >= o) v += t;
    }
    __shared__ int wsum[32];
    if (lane == 31) wsum[wid] = v;
    __syncthreads();
    if (wid == 0) {
        int w = wsum[lane];
        #pragma unroll
        for (int o = 1; o < 32; o <<= 1) {
            int t = __shfl_up_sync(0xffffffffu, w, o);
            if (lane >= o) w += t;
        }
        wsum[lane] = w;
    }
    __syncthreads();
    int excl = v - sum + (wid ? wsum[wid - 1] : 0);

    int run = excl;
    for (int i = start; i < stop; i++) { g_off[i] = run; run += g_deg[i]; }
    if (tid == 1023) g_off[NN] = run;
}

// fill CSR + precompute hd1/hd2 (captured by ncu this round)
__global__ void k_fill(const int* __restrict__ ei, const float* __restrict__ ea) {
    __shared__ float wv1[ED], wv2[ED];
    if (threadIdx.x < ED) wv1[threadIdx.x] = g_wvec1[threadIdx.x];
    else if (threadIdx.x < 2 * ED) wv2[threadIdx.x - ED] = g_wvec2[threadIdx.x - ED];
    __syncthreads();
    int e = blockIdx.x * blockDim.x + threadIdx.x;
    if (e >= NE) return;
    int src = ei[e], dst = ei[NE + e];
    const float4* ea4 = (const float4*)(ea + (size_t)e * ED);
    float h1 = 0.f, h2 = 0.f;
    #pragma unroll
    for (int i = 0; i < ED / 4; i++) {
        float4 v = ea4[i];
        float4 w1 = ((const float4*)wv1)[i];
        float4 w2 = ((const float4*)wv2)[i];
        h1 += v.x * w1.x + v.y * w1.y + v.z * w1.z + v.w * w1.w;
        h2 += v.x * w2.x + v.y * w2.y + v.z * w2.z + v.w * w2.w;
    }
    int pos = g_off[dst] + atomicAdd(&g_cnt[dst], 1);
    g_src_csr[pos] = src;
    g_hd1[pos] = h1;
    g_hd2[pos] = h2;
}

// ---------------- node GEMM (R5 version, known 64.7us): h = x@W, s_src, s_dst ----------------
template <int K>
__global__ __launch_bounds__(256) void k_layer_gemm(
    const float* xext, const float* __restrict__ W,
    const float* __restrict__ avs, const float* __restrict__ avd, int use_internal)
{
    __shared__ float Ws[K * HID];
    __shared__ float xs[16 * K];
    const float* x = use_internal ? (const float*)g_x1 : xext;
    int tid = threadIdx.x;
    for (int i = tid; i < K * HID; i += 256) Ws[i] = W[i];

    int r = tid >> 4, c = tid & 15;
    float4 as4 = ((const float4*)avs)[c];
    float4 ad4 = ((const float4*)avd)[c];

    for (int base = blockIdx.x * 16; base < NN; base += gridDim.x * 16) {
        __syncthreads();
        for (int i = tid; i < 16 * K; i += 256) xs[i] = x[(size_t)base * K + i];
        __syncthreads();

        float4 acc = make_float4(0.f, 0.f, 0.f, 0.f);
        const float* xr = &xs[r * K];
        #pragma unroll
        for (int k = 0; k < K; k++) {
            float xv = xr[k];
            float4 w = ((const float4*)Ws)[k * 16 + c];
            acc.x += xv * w.x; acc.y += xv * w.y; acc.z += xv * w.z; acc.w += xv * w.w;
        }
        int n = base + r;
        ((float4*)g_h)[n * 16 + c] = acc;

        float ps = acc.x * as4.x + acc.y * as4.y + acc.z * as4.z + acc.w * as4.w;
        float pd = acc.x * ad4.x + acc.y * ad4.y + acc.z * ad4.z + acc.w * ad4.w;
        #pragma unroll
        for (int o = 8; o > 0; o >>= 1) {
            ps += __shfl_down_sync(0xffffffffu, ps, o, 16);
            pd += __shfl_down_sync(0xffffffffu, pd, o, 16);
        }
        if (c == 0) { g_ssrc[n] = ps; g_sdst[n] = pd; }
    }
}

// ---------------- warp-per-node SINGLE-PASS softmax aggregation (R5) ----------------
__global__ __launch_bounds__(256) void k_agg(const float* __restrict__ hd,
                                             const float* __restrict__ bias,
                                             float* __restrict__ xout)
{
    int n = (blockIdx.x * blockDim.x + threadIdx.x) >> 5;
    int lane = threadIdx.x & 31;
    if (n >= NN) return;
    int beg = g_off[n];
    int end = g_off[n + 1];
    float sdst_n = g_sdst[n];

    float hds = 0.f, dl = 0.f;
    float accx = 0.f, accy = 0.f;   // lane owns cols {2*lane, 2*lane+1}

    for (int cb = beg; cb < end; cb += 32) {
        int j = cb + lane;
        bool valid = j < end;
        int sl = valid ? g_src_csr[j] : 0;
        float el = 0.f;
        if (valid) {
            float hdv = hd[j];
            hds += hdv;
            el = expf(lrelu(g_ssrc[sl] + sdst_n + hdv));
        }
        dl += el;
        int cnt = min(32, end - cb);
        #pragma unroll 4
        for (int k = 0; k < cnt; k++) {
            float ex = __shfl_sync(0xffffffffu, el, k);
            int s = __shfl_sync(0xffffffffu, sl, k);
            float2 hv = *(const float2*)&g_h[s * HID + 2 * lane];
            accx += ex * hv.x;
            accy += ex * hv.y;
        }
    }
    #pragma unroll
    for (int o = 16; o > 0; o >>= 1) {
        hds += __shfl_xor_sync(0xffffffffu, hds, o);
        dl  += __shfl_xor_sync(0xffffffffu, dl, o);
    }
    int deg = end - beg;
    float ld = hds / fmaxf((float)deg, 1.f);
    float exl = expf(lrelu(g_ssrc[n] + sdst_n + ld));
    dl += exl;
    float2 hn = *(const float2*)&g_h[n * HID + 2 * lane];
    accx += exl * hn.x;
    accy += exl * hn.y;

    float inv = 1.f / dl;
    float2 b2v = *(const float2*)&bias[2 * lane];
    float2 o;
    o.x = fmaxf(accx * inv + b2v.x, 0.f);
    o.y = fmaxf(accy * inv + b2v.y, 0.f);
    *(float2*)&xout[n * HID + 2 * lane] = o;
}

// ---------------- p/q dual GEMM (R5 version) ----------------
__global__ __launch_bounds__(256) void k_pq(const float* __restrict__ Wc1,
                                            const float* __restrict__ bc1)
{
    __shared__ float Wp[HID * HID];
    __shared__ float Wq[HID * HID];
    __shared__ float xs[16 * HID];
    int tid = threadIdx.x;
    for (int i = tid; i < HID * HID; i += 256) {
        Wp[i] = Wc1[i];
        Wq[i] = Wc1[HID * HID + i];
    }
    int r = tid >> 4, c = tid & 15;
    float4 b4 = ((const float4*)bc1)[c];

    for (int base = blockIdx.x * 16; base < NN; base += gridDim.x * 16) {
        __syncthreads();
        for (int i = tid; i < 16 * HID; i += 256) xs[i] = g_x2[(size_t)base * HID + i];
        __syncthreads();

        float4 ap = b4;
        float4 aq = make_float4(0.f, 0.f, 0.f, 0.f);
        const float* xr = &xs[r * HID];
        #pragma unroll
        for (int k = 0; k < HID; k++) {
            float xv = xr[k];
            float4 wp = ((const float4*)Wp)[k * 16 + c];
            float4 wq = ((const float4*)Wq)[k * 16 + c];
            ap.x += xv * wp.x; ap.y += xv * wp.y; ap.z += xv * wp.z; ap.w += xv * wp.w;
            aq.x += xv * wq.x; aq.y += xv * wq.y; aq.z += xv * wq.z; aq.w += xv * wq.w;
        }
        int n = base + r;
        ((float4*)g_p)[n * 16 + c] = ap;
        ((float4*)g_q)[n * 16 + c] = aq;
    }
}

// ---------------- final edge MLP: 2 threads/edge, conflict-free padded smem + FFMA2 ----
// Ws layout: [k][half*36 + c], c in 0..31. Half offset = 144B (bank shift 4, 16B-aligned)
// so the two halves within one LDS.128 never collide. Row stride 288B.
__global__ __launch_bounds__(256) void k_final(
    const int* __restrict__ ei, const float* __restrict__ ea,
    const float* __restrict__ Wc1, const float* __restrict__ Wc2,
    const float* __restrict__ bc2, float* __restrict__ out)
{
    __shared__ float Ws[ED * 72];    // [32][72]
    __shared__ float wc2s[2 * 36];   // [half][36]
    int tid = threadIdx.x;
    for (int i = tid; i < ED * HID; i += 256) {
        int k = i >> 6, col = i & 63;
        Ws[k * 72 + (col >> 5) * 36 + (col & 31)] = Wc1[2 * HID * HID + i];
    }
    if (tid < HID) wc2s[(tid >> 5) * 36 + (tid & 31)] = Wc2[tid];
    __syncthreads();

    int t = blockIdx.x * 256 + tid;
    int e = t >> 1;
    int half = t & 1;
    if (e >= NE) return;
    int src = ei[e], dst = ei[NE + e];

    float4 A[8];
    const float4* ea4 = (const float4*)(ea + (size_t)e * ED);
    #pragma unroll
    for (int i = 0; i < 8; i++) A[i] = ea4[i];
    const float* a = (const float*)A;

    unsigned long long acc[16];
    #pragma unroll
    for (int j = 0; j < 16; j++) acc[j] = 0ull;

    #pragma unroll
    for (int k = 0; k < ED; k++) {
        unsigned long long ak = dup2(a[k]);
        const ulonglong2* wrow = (const ulonglong2*)&Ws[k * 72 + half * 36];
        #pragma unroll
        for (int j = 0; j < 8; j++) {
            ulonglong2 w = wrow[j];
            fma2(acc[2 * j], ak, w.x);
            fma2(acc[2 * j + 1], ak, w.y);
        }
    }

    const float4* p4 = (const float4*)&g_p[src * HID + half * 32];
    const float4* q4 = (const float4*)&g_q[dst * HID + half * 32];
    const float4* w4 = (const float4*)&wc2s[half * 36];
    float s = 0.f;
    #pragma unroll
    for (int j = 0; j < 8; j++) {
        float2 a0 = unp(acc[2 * j]);
        float2 a1 = unp(acc[2 * j + 1]);
        float4 pv = p4[j], qv = q4[j], wv = w4[j];
        float hx = fmaxf(pv.x + qv.x + a0.x, 0.f);
        float hy = fmaxf(pv.y + qv.y + a0.y, 0.f);
        float hz = fmaxf(pv.z + qv.z + a1.x, 0.f);
        float hw = fmaxf(pv.w + qv.w + a1.y, 0.f);
        s += hx * wv.x + hy * wv.y + hz * wv.z + hw * wv.w;
    }
    s += __shfl_down_sync(0xffffffffu, s, 1);
    if (half == 0) out[e] = s + bc2[0];
}

// ---------------- launch sequence ----------------
extern "C" void kernel_launch(void* const* d_in, const int* in_sizes, int n_in,
                              void* d_out, int out_size)
{
    const float* x   = (const float*)d_in[0];
    const int*   ei  = (const int*)d_in[1];
    const float* ea  = (const float*)d_in[2];
    const float* W1  = (const float*)d_in[3];
    const float* We1 = (const float*)d_in[4];
    const float* as1 = (const float*)d_in[5];
    const float* ad1 = (const float*)d_in[6];
    const float* ae1 = (const float*)d_in[7];
    const float* b1  = (const float*)d_in[8];
    const float* W2  = (const float*)d_in[9];
    const float* We2 = (const float*)d_in[10];
    const float* as2 = (const float*)d_in[11];
    const float* ad2 = (const float*)d_in[12];
    const float* ae2 = (const float*)d_in[13];
    const float* b2  = (const float*)d_in[14];
    const float* Wc1 = (const float*)d_in[15];
    const float* bc1 = (const float*)d_in[16];
    const float* Wc2 = (const float*)d_in[17];
    const float* bc2 = (const float*)d_in[18];
    float* out = (float*)d_out;

    const int TB = 256;
    const int NB_E   = (NE + TB - 1) / TB;
    const int NB_AGG = (NN * 32 + TB - 1) / TB;
    const int NB_FIN = (NE * 2 + TB - 1) / TB;
    const int NB_GEMM = 1184;

    float* g_x1p; cudaGetSymbolAddress((void**)&g_x1p, g_x1);
    float* g_x2p; cudaGetSymbolAddress((void**)&g_x2p, g_x2);
    float* g_hd1p; cudaGetSymbolAddress((void**)&g_hd1p, g_hd1);
    float* g_hd2p; cudaGetSymbolAddress((void**)&g_hd2p, g_hd2);

    // 4th launch = k_fill (ncu capture slot): first profile of an edge pass
    k_zw<<<197, TB>>>(We1, ae1, We2, ae2);                              // 1 (zero + wvec)
    k_count_deg<<<NB_E, TB>>>(ei);                                      // 2
    k_scan<<<1, 1024>>>();                                              // 3
    k_fill<<<NB_E, TB>>>(ei, ea);                                       // 4 <- profiled

    k_layer_gemm<IN_DIM><<<NB_GEMM, TB>>>(x, W1, as1, ad1, 0);          // 5
    k_agg<<<NB_AGG, TB>>>(g_hd1p, b1, g_x1p);                           // 6

    k_layer_gemm<HID><<<NB_GEMM, TB>>>(x, W2, as2, ad2, 1);             // 7
    k_agg<<<NB_AGG, TB>>>(g_hd2p, b2, g_x2p);                           // 8

    k_pq<<<NB_GEMM, TB>>>(Wc1, bc1);                                    // 9
    k_final<<<NB_FIN, TB>>>(ei, ea, Wc1, Wc2, bc2, out);                // 10
}

// round 12
// speedup vs baseline: 1.6952x; 1.0244x over previous
#include <cuda_runtime.h>
#include <math.h>
#include <stdint.h>

#define NN 50000
#define NE 800000
#define HID 64
#define IN_DIM 128
#define ED 32
#define NEG 0.2f

// ---------------- device scratch (static-zero init is load-bearing for g_deg/g_cnt) ----
__device__ __align__(16) float g_h[NN * HID];
__device__ __align__(16) float g_x1[NN * HID];
__device__ __align__(16) float g_x2[NN * HID];
__device__ __align__(16) float g_p[NN * HID];
__device__ __align__(16) float g_q[NN * HID];
__device__ float g_ssrc[NN];
__device__ float g_sdst[NN];
__device__ int g_deg[NN];     // zeroed by k_tail each call (static init covers call #1)
__device__ int g_cnt[NN];     // same
__device__ int g_off[NN + 1];
__device__ int g_src_csr[NE];
__device__ float g_hd1[NE];
__device__ float g_hd2[NE];
__device__ float g_wvec1[ED];
__device__ float g_wvec2[ED];

__device__ __forceinline__ float lrelu(float x) { return x > 0.f ? x : NEG * x; }

__device__ __forceinline__ void fma2(unsigned long long& d, unsigned long long a,
                                     unsigned long long b) {
    asm("fma.rn.f32x2 %0, %1, %2, %0;" : "+l"(d) : "l"(a), "l"(b));
}
__device__ __forceinline__ unsigned long long dup2(float v) {
    unsigned long long d;
    unsigned u = __float_as_uint(v);
    asm("mov.b64 %0, {%1, %1};" : "=l"(d) : "r"(u));
    return d;
}
__device__ __forceinline__ float2 unp(unsigned long long v) {
    unsigned lo, hi;
    asm("mov.b64 {%0, %1}, %2;" : "=r"(lo), "=r"(hi) : "l"(v));
    return make_float2(__uint_as_float(lo), __uint_as_float(hi));
}

// ---------------- scan + wvec fused (single block) ----------------
__global__ __launch_bounds__(1024) void k_scanw(
    const float* __restrict__ We1, const float* __restrict__ ae1,
    const float* __restrict__ We2, const float* __restrict__ ae2)
{
    int tid = threadIdx.x;
    // wvec: threads 0..255, 4 threads per output
    if (tid < 256) {
        int o = tid >> 2, q = tid & 3;
        const float* We = (o < ED) ? We1 : We2;
        const float* ae = (o < ED) ? ae1 : ae2;
        int k = (o < ED) ? o : o - ED;
        float s = 0.f;
        for (int j = q; j < HID; j += 4) s += We[k * HID + j] * ae[j];
        s += __shfl_down_sync(0xffffffffu, s, 2, 4);
        s += __shfl_down_sync(0xffffffffu, s, 1, 4);
        if (q == 0) { if (o < ED) g_wvec1[o] = s; else g_wvec2[o - ED] = s; }
    }

    // exclusive scan of g_deg -> g_off
    const int PER = (NN + 1023) / 1024;   // 49
    int lane = tid & 31, wid = tid >> 5;
    int start = tid * PER;
    int stop = min(start + PER, NN);

    int sum = 0;
    for (int i = start; i < stop; i++) sum += g_deg[i];

    int v = sum;
    #pragma unroll
    for (int o = 1; o < 32; o <<= 1) {
        int t = __shfl_up_sync(0xffffffffu, v, o);
        if (lane >= o) v += t;
    }
    __shared__ int wsum[32];
    if (lane == 31) wsum[wid] = v;
    __syncthreads();
    if (wid == 0) {
        int w = wsum[lane];
        #pragma unroll
        for (int o = 1; o < 32; o <<= 1) {
            int t = __shfl_up_sync(0xffffffffu, w, o);
            if (lane >= o) w += t;
        }
        wsum[lane] = w;
    }
    __syncthreads();
    int excl = v - sum + (wid ? wsum[wid - 1] : 0);

    int run = excl;
    for (int i = start; i < stop; i++) { g_off[i] = run; run += g_deg[i]; }
    if (tid == 1023) g_off[NN] = run;
}

// fill CSR + precompute hd1/hd2
__global__ void k_fill(const int* __restrict__ ei, const float* __restrict__ ea) {
    __shared__ float wv1[ED], wv2[ED];
    if (threadIdx.x < ED) wv1[threadIdx.x] = g_wvec1[threadIdx.x];
    else if (threadIdx.x < 2 * ED) wv2[threadIdx.x - ED] = g_wvec2[threadIdx.x - ED];
    __syncthreads();
    int e = blockIdx.x * blockDim.x + threadIdx.x;
    if (e >= NE) return;
    int src = ei[e], dst = ei[NE + e];
    const float4* ea4 = (const float4*)(ea + (size_t)e * ED);
    float h1 = 0.f, h2 = 0.f;
    #pragma unroll
    for (int i = 0; i < ED / 4; i++) {
        float4 v = ea4[i];
        float4 w1 = ((const float4*)wv1)[i];
        float4 w2 = ((const float4*)wv2)[i];
        h1 += v.x * w1.x + v.y * w1.y + v.z * w1.z + v.w * w1.w;
        h2 += v.x * w2.x + v.y * w2.y + v.z * w2.z + v.w * w2.w;
    }
    int pos = g_off[dst] + atomicAdd(&g_cnt[dst], 1);
    g_src_csr[pos] = src;
    g_hd1[pos] = h1;
    g_hd2[pos] = h2;
}

// ---------------- node GEMM (+ optional degree count folded in) ----------------
template <int K>
__global__ __launch_bounds__(256) void k_layer_gemm(
    const float* xext, const float* __restrict__ W,
    const float* __restrict__ avs, const float* __restrict__ avd,
    int use_internal, const int* __restrict__ ei)
{
    __shared__ float Ws[K * HID];
    __shared__ float xs[16 * K];
    const float* x = use_internal ? (const float*)g_x1 : xext;
    int tid = threadIdx.x;

    // fire-and-forget degree count (layer 1 only) — overlaps with GEMM
    if (ei) {
        for (int e = blockIdx.x * 256 + tid; e < NE; e += gridDim.x * 256)
            atomicAdd(&g_deg[ei[NE + e]], 1);
    }

    for (int i = tid; i < K * HID; i += 256) Ws[i] = W[i];

    int r = tid >> 4, c = tid & 15;
    float4 as4 = ((const float4*)avs)[c];
    float4 ad4 = ((const float4*)avd)[c];

    for (int base = blockIdx.x * 16; base < NN; base += gridDim.x * 16) {
        __syncthreads();
        for (int i = tid; i < 16 * K; i += 256) xs[i] = x[(size_t)base * K + i];
        __syncthreads();

        float4 acc = make_float4(0.f, 0.f, 0.f, 0.f);
        const float* xr = &xs[r * K];
        #pragma unroll
        for (int k = 0; k < K; k++) {
            float xv = xr[k];
            float4 w = ((const float4*)Ws)[k * 16 + c];
            acc.x += xv * w.x; acc.y += xv * w.y; acc.z += xv * w.z; acc.w += xv * w.w;
        }
        int n = base + r;
        ((float4*)g_h)[n * 16 + c] = acc;

        float ps = acc.x * as4.x + acc.y * as4.y + acc.z * as4.z + acc.w * as4.w;
        float pd = acc.x * ad4.x + acc.y * ad4.y + acc.z * ad4.z + acc.w * ad4.w;
        #pragma unroll
        for (int o = 8; o > 0; o >>= 1) {
            ps += __shfl_down_sync(0xffffffffu, ps, o, 16);
            pd += __shfl_down_sync(0xffffffffu, pd, o, 16);
        }
        if (c == 0) { g_ssrc[n] = ps; g_sdst[n] = pd; }
    }
}

// ---------------- k_agg v2: warp/node, half-warp per edge, smem-staged pairs ----------
// Per 2 edges: 1 LDS.64 bcast + 1 LDG.128 + 2 FFMA2  (was ~10 slots for 2 edges).
__global__ __launch_bounds__(256) void k_agg(const float* __restrict__ hd,
                                             const float* __restrict__ bias,
                                             float* __restrict__ xout)
{
    __shared__ unsigned long long s_pair[8][32];
    int wid = threadIdx.x >> 5;
    int lane = threadIdx.x & 31;
    int n = (blockIdx.x * blockDim.x + threadIdx.x) >> 5;
    if (n >= NN) return;
    int beg = g_off[n];
    int end = g_off[n + 1];
    float sdst_n = g_sdst[n];

    int colbase = 4 * (lane & 15);
    int half = lane >> 4;
    float hds = 0.f, dl = 0.f;
    unsigned long long acc0 = 0ull, acc1 = 0ull;   // cols colbase..colbase+3

    for (int cb = beg; cb < end; cb += 32) {
        int j = cb + lane;
        bool valid = j < end;
        int sl = 0; float el = 0.f;
        if (valid) {
            float hdv = hd[j];
            hds += hdv;
            sl = g_src_csr[j];
            el = expf(lrelu(g_ssrc[sl] + sdst_n + hdv));
        }
        dl += el;
        s_pair[wid][lane] = ((unsigned long long)__float_as_uint(el) << 32) | (unsigned)sl;
        __syncwarp();

        int cnt = min(32, end - cb);
        for (int k = 0; k < cnt; k += 2) {
            int idx = k + half;
            unsigned long long pp = s_pair[wid][min(idx, cnt - 1)];
            float ev = (idx < cnt) ? __uint_as_float((unsigned)(pp >> 32)) : 0.f;
            int sv = (int)(unsigned)(pp & 0xffffffffu);
            const ulonglong2* hv = (const ulonglong2*)&g_h[(size_t)sv * HID + colbase];
            ulonglong2 h2 = *hv;
            unsigned long long ev2 = dup2(ev);
            fma2(acc0, ev2, h2.x);
            fma2(acc1, ev2, h2.y);
        }
        __syncwarp();
    }

    #pragma unroll
    for (int o = 16; o > 0; o >>= 1) {
        hds += __shfl_xor_sync(0xffffffffu, hds, o);
        dl  += __shfl_xor_sync(0xffffffffu, dl, o);
    }
    int deg = end - beg;
    float ld = hds / fmaxf((float)deg, 1.f);
    float exl = expf(lrelu(g_ssrc[n] + sdst_n + ld));
    dl += exl;

    // combine halves (both halves end with the full sum)
    float2 a0 = unp(acc0), a1 = unp(acc1);
    float4 a = make_float4(a0.x, a0.y, a1.x, a1.y);
    a.x += __shfl_xor_sync(0xffffffffu, a.x, 16);
    a.y += __shfl_xor_sync(0xffffffffu, a.y, 16);
    a.z += __shfl_xor_sync(0xffffffffu, a.z, 16);
    a.w += __shfl_xor_sync(0xffffffffu, a.w, 16);

    // self loop
    float4 hn = *(const float4*)&g_h[(size_t)n * HID + colbase];
    a.x += exl * hn.x; a.y += exl * hn.y; a.z += exl * hn.z; a.w += exl * hn.w;

    if (lane < 16) {
        float inv = 1.f / dl;
        float4 b4 = ((const float4*)bias)[lane];
        float4 o;
        o.x = fmaxf(a.x * inv + b4.x, 0.f);
        o.y = fmaxf(a.y * inv + b4.y, 0.f);
        o.z = fmaxf(a.z * inv + b4.z, 0.f);
        o.w = fmaxf(a.w * inv + b4.w, 0.f);
        ((float4*)xout)[n * 16 + lane] = o;
    }
}

// ---------------- p/q dual GEMM (unchanged R5) ----------------
__global__ __launch_bounds__(256) void k_pq(const float* __restrict__ Wc1,
                                            const float* __restrict__ bc1)
{
    __shared__ float Wp[HID * HID];
    __shared__ float Wq[HID * HID];
    __shared__ float xs[16 * HID];
    int tid = threadIdx.x;
    for (int i = tid; i < HID * HID; i += 256) {
        Wp[i] = Wc1[i];
        Wq[i] = Wc1[HID * HID + i];
    }
    int r = tid >> 4, c = tid & 15;
    float4 b4 = ((const float4*)bc1)[c];

    for (int base = blockIdx.x * 16; base < NN; base += gridDim.x * 16) {
        __syncthreads();
        for (int i = tid; i < 16 * HID; i += 256) xs[i] = g_x2[(size_t)base * HID + i];
        __syncthreads();

        float4 ap = b4;
        float4 aq = make_float4(0.f, 0.f, 0.f, 0.f);
        const float* xr = &xs[r * HID];
        #pragma unroll
        for (int k = 0; k < HID; k++) {
            float xv = xr[k];
            float4 wp = ((const float4*)Wp)[k * 16 + c];
            float4 wq = ((const float4*)Wq)[k * 16 + c];
            ap.x += xv * wp.x; ap.y += xv * wp.y; ap.z += xv * wp.z; ap.w += xv * wp.w;
            aq.x += xv * wq.x; aq.y += xv * wq.y; aq.z += xv * wq.z; aq.w += xv * wq.w;
        }
        int n = base + r;
        ((float4*)g_p)[n * 16 + c] = ap;
        ((float4*)g_q)[n * 16 + c] = aq;
    }
}

// ---------------- final edge MLP (unchanged R10: conflict-free + FFMA2) ----------------
__global__ __launch_bounds__(256) void k_final(
    const int* __restrict__ ei, const float* __restrict__ ea,
    const float* __restrict__ Wc1, const float* __restrict__ Wc2,
    const float* __restrict__ bc2, float* __restrict__ out)
{
    __shared__ float Ws[ED * 72];
    __shared__ float wc2s[2 * 36];
    int tid = threadIdx.x;
    for (int i = tid; i < ED * HID; i += 256) {
        int k = i >> 6, col = i & 63;
        Ws[k * 72 + (col >> 5) * 36 + (col & 31)] = Wc1[2 * HID * HID + i];
    }
    if (tid < HID) wc2s[(tid >> 5) * 36 + (tid & 31)] = Wc2[tid];
    __syncthreads();

    int t = blockIdx.x * 256 + tid;
    int e = t >> 1;
    int half = t & 1;
    if (e >= NE) return;
    int src = ei[e], dst = ei[NE + e];

    float4 A[8];
    const float4* ea4 = (const float4*)(ea + (size_t)e * ED);
    #pragma unroll
    for (int i = 0; i < 8; i++) A[i] = ea4[i];
    const float* a = (const float*)A;

    unsigned long long acc[16];
    #pragma unroll
    for (int j = 0; j < 16; j++) acc[j] = 0ull;

    #pragma unroll
    for (int k = 0; k < ED; k++) {
        unsigned long long ak = dup2(a[k]);
        const ulonglong2* wrow = (const ulonglong2*)&Ws[k * 72 + half * 36];
        #pragma unroll
        for (int j = 0; j < 8; j++) {
            ulonglong2 w = wrow[j];
            fma2(acc[2 * j], ak, w.x);
            fma2(acc[2 * j + 1], ak, w.y);
        }
    }

    const float4* p4 = (const float4*)&g_p[src * HID + half * 32];
    const float4* q4 = (const float4*)&g_q[dst * HID + half * 32];
    const float4* w4 = (const float4*)&wc2s[half * 36];
    float s = 0.f;
    #pragma unroll
    for (int j = 0; j < 8; j++) {
        float2 a0 = unp(acc[2 * j]);
        float2 a1 = unp(acc[2 * j + 1]);
        float4 pv = p4[j], qv = q4[j], wv = w4[j];
        float hx = fmaxf(pv.x + qv.x + a0.x, 0.f);
        float hy = fmaxf(pv.y + qv.y + a0.y, 0.f);
        float hz = fmaxf(pv.z + qv.z + a1.x, 0.f);
        float hw = fmaxf(pv.w + qv.w + a1.y, 0.f);
        s += hx * wv.x + hy * wv.y + hz * wv.z + hw * wv.w;
    }
    s += __shfl_down_sync(0xffffffffu, s, 1);
    if (half == 0) out[e] = s + bc2[0];
}

// tail: re-zero deg/cnt for the NEXT invocation (first call relies on static init)
__global__ void k_tail() {
    int n = blockIdx.x * blockDim.x + threadIdx.x;
    if (n < NN) { g_deg[n] = 0; g_cnt[n] = 0; }
}

// ---------------- launch sequence ----------------
extern "C" void kernel_launch(void* const* d_in, const int* in_sizes, int n_in,
                              void* d_out, int out_size)
{
    const float* x   = (const float*)d_in[0];
    const int*   ei  = (const int*)d_in[1];
    const float* ea  = (const float*)d_in[2];
    const float* W1  = (const float*)d_in[3];
    const float* We1 = (const float*)d_in[4];
    const float* as1 = (const float*)d_in[5];
    const float* ad1 = (const float*)d_in[6];
    const float* ae1 = (const float*)d_in[7];
    const float* b1  = (const float*)d_in[8];
    const float* W2  = (const float*)d_in[9];
    const float* We2 = (const float*)d_in[10];
    const float* as2 = (const float*)d_in[11];
    const float* ad2 = (const float*)d_in[12];
    const float* ae2 = (const float*)d_in[13];
    const float* b2  = (const float*)d_in[14];
    const float* Wc1 = (const float*)d_in[15];
    const float* bc1 = (const float*)d_in[16];
    const float* Wc2 = (const float*)d_in[17];
    const float* bc2 = (const float*)d_in[18];
    float* out = (float*)d_out;

    const int TB = 256;
    const int NB_N   = (NN + TB - 1) / TB;
    const int NB_E   = (NE + TB - 1) / TB;
    const int NB_AGG = (NN * 32 + TB - 1) / TB;
    const int NB_FIN = (NE * 2 + TB - 1) / TB;
    const int NB_GEMM = 1184;

    float* g_x1p; cudaGetSymbolAddress((void**)&g_x1p, g_x1);
    float* g_x2p; cudaGetSymbolAddress((void**)&g_x2p, g_x2);
    float* g_hd1p; cudaGetSymbolAddress((void**)&g_hd1p, g_hd1);
    float* g_hd2p; cudaGetSymbolAddress((void**)&g_hd2p, g_hd2);

    // slot 4 = k_agg (ncu capture): first profile of the suspected dominant kernel
    k_layer_gemm<IN_DIM><<<NB_GEMM, TB>>>(x, W1, as1, ad1, 0, ei);  // 1 (GEMM + deg count)
    k_scanw<<<1, 1024>>>(We1, ae1, We2, ae2);                       // 2 (scan + wvec)
    k_fill<<<NB_E, TB>>>(ei, ea);                                   // 3
    k_agg<<<NB_AGG, TB>>>(g_hd1p, b1, g_x1p);                       // 4 <- profiled

    k_layer_gemm<HID><<<NB_GEMM, TB>>>(x, W2, as2, ad2, 1, nullptr);// 5
    k_agg<<<NB_AGG, TB>>>(g_hd2p, b2, g_x2p);                       // 6

    k_pq<<<NB_GEMM, TB>>>(Wc1, bc1);                                // 7
    k_final<<<NB_FIN, TB>>>(ei, ea, Wc1, Wc2, bc2, out);            // 8
    k_tail<<<NB_N, TB>>>();                                         // 9 (re-zero for next call)
}